// round 7
// baseline (speedup 1.0000x reference)
#include <cuda_runtime.h>
#include <cuda_bf16.h>
#include <math.h>
#include <stdint.h>

#define B_SZ 512
#define D_SZ 512
#define C_SZ 100000
#define BN 128
#define BM 128
#define BK 64
#define NK 8                       // 512/64
#define NSTAGE 4
#define NTILES_N 782               // ceil(100000/128)
#define C_PAD (NTILES_N * BN)      // 100096 (pad rows stay zero)
#define PITCH 72                   // halves per smem row (144 B) — conflict-free ldsm
#define STAGE_B (2 * 128 * PITCH * 2)      // A half + B half = 36864 B
#define B_PART  (128 * PITCH * 2)          // 18432
#define SMEM_BYTES (NSTAGE * STAGE_B)      // 147456
#define S_SCALE 30.0f
#define LMAX 31.0f
#define COS_M 0.8775825618903728f
#define SIN_M 0.47942553860420300f

// ---------------- static device scratch -------------------------------------
__device__ __nv_bfloat16 g_wn[(size_t)C_PAD * D_SZ];   // normalized bf16 w
__device__ __nv_bfloat16 g_xnbf[B_SZ * D_SZ];
__device__ float g_xn[B_SZ * D_SZ];
__device__ float g_rowsum[B_SZ];
__device__ float g_nll[B_SZ];

// ---------------- PTX helpers ------------------------------------------------
__device__ __forceinline__ uint32_t smem_u32(const void* p) {
    uint32_t a;
    asm("{ .reg .u64 t; cvta.to.shared.u64 t, %1; cvt.u32.u64 %0, t; }" : "=r"(a) : "l"(p));
    return a;
}
__device__ __forceinline__ void cp16(uint32_t dst, const void* src) {
    asm volatile("cp.async.cg.shared.global [%0], [%1], 16;" :: "r"(dst), "l"(src));
}
#define CP_COMMIT() asm volatile("cp.async.commit_group;" ::: "memory")
#define CP_WAIT(n)  asm volatile("cp.async.wait_group %0;" :: "n"(n) : "memory")

__device__ __forceinline__ void ldsm4(uint32_t* r, uint32_t addr) {
    asm volatile("ldmatrix.sync.aligned.m8n8.x4.shared.b16 {%0,%1,%2,%3}, [%4];"
        : "=r"(r[0]), "=r"(r[1]), "=r"(r[2]), "=r"(r[3]) : "r"(addr));
}
__device__ __forceinline__ void mma16816(float* d, const uint32_t* a, uint32_t b0, uint32_t b1) {
    asm volatile(
        "mma.sync.aligned.m16n8k16.row.col.f32.bf16.bf16.f32 "
        "{%0,%1,%2,%3}, {%4,%5,%6,%7}, {%8,%9}, {%0,%1,%2,%3};"
        : "+f"(d[0]), "+f"(d[1]), "+f"(d[2]), "+f"(d[3])
        : "r"(a[0]), "r"(a[1]), "r"(a[2]), "r"(a[3]), "r"(b0), "r"(b1));
}

// ---------------------------------------------------------------------------
// Kernel 1: normalize x rows -> g_xn (fp32) + g_xnbf (bf16); zero g_rowsum
// ---------------------------------------------------------------------------
__global__ void xnorm_kernel(const float* __restrict__ x) {
    const int row = blockIdx.x;
    const int tid = threadIdx.x;   // 128
    const float* xr = x + (size_t)row * D_SZ;

    float ss = 0.f;
    float v[4];
    #pragma unroll
    for (int i = 0; i < 4; i++) { v[i] = xr[tid + i * 128]; ss += v[i] * v[i]; }
    __shared__ float red[128];
    red[tid] = ss;
    __syncthreads();
    #pragma unroll
    for (int off = 64; off > 0; off >>= 1) {
        if (tid < off) red[tid] += red[tid + off];
        __syncthreads();
    }
    const float inv = 1.f / fmaxf(sqrtf(red[0]), 1e-12f);
    #pragma unroll
    for (int i = 0; i < 4; i++) {
        int d = tid + i * 128;
        float nv = v[i] * inv;
        g_xn[(size_t)row * D_SZ + d] = nv;
        g_xnbf[(size_t)row * D_SZ + d] = __float2bfloat16_rn(nv);
    }
    if (tid == 0) g_rowsum[row] = 0.f;
}

// ---------------------------------------------------------------------------
// Kernel 2: normalize weight rows + convert to bf16 (one warp per row)
// ---------------------------------------------------------------------------
__global__ void wconv_kernel(const float* __restrict__ w) {
    const int warp = threadIdx.x >> 5;
    const int lane = threadIdx.x & 31;
    const int c = blockIdx.x * 8 + warp;       // grid 12500 -> 100000 rows
    const float4* wr = reinterpret_cast<const float4*>(w + (size_t)c * D_SZ);

    float4 v[4];
    float ss = 0.f;
    #pragma unroll
    for (int i = 0; i < 4; i++) {
        v[i] = wr[lane + i * 32];
        ss += v[i].x * v[i].x + v[i].y * v[i].y + v[i].z * v[i].z + v[i].w * v[i].w;
    }
    #pragma unroll
    for (int m = 16; m > 0; m >>= 1)
        ss += __shfl_xor_sync(0xffffffffu, ss, m);
    const float inv = 1.f / fmaxf(sqrtf(ss), 1e-12f);

    uint2* dst = reinterpret_cast<uint2*>(g_wn + (size_t)c * D_SZ);
    #pragma unroll
    for (int i = 0; i < 4; i++) {
        __nv_bfloat162 p0 = __floats2bfloat162_rn(v[i].x * inv, v[i].y * inv);
        __nv_bfloat162 p1 = __floats2bfloat162_rn(v[i].z * inv, v[i].w * inv);
        uint2 o;
        o.x = *reinterpret_cast<uint32_t*>(&p0);
        o.y = *reinterpret_cast<uint32_t*>(&p1);
        dst[lane + i * 32] = o;
    }
}

// ---------------------------------------------------------------------------
// Kernel 3: fused HMMA GEMM + streaming exp-sum epilogue.
// CTA 128x128xK512. 4-stage cp.async ring, BK=64, ONE barrier per k-step
// (wait -> sync -> issue load k+3 -> compute k).
// Grid (m=4, n=782): the 4 CTAs sharing a B tile are consecutive -> L2 reuse.
// ---------------------------------------------------------------------------
__global__ void __launch_bounds__(256, 1) gemm_fused_kernel() {
    extern __shared__ __align__(16) char smem[];
    const int tid = threadIdx.x;
    const int warp = tid >> 5;
    const int lane = tid & 31;
    const int wm = warp & 1;
    const int wn = warp >> 1;
    const int m0 = blockIdx.x * BM;
    const int n0 = blockIdx.y * BN;
    const uint32_t sb = smem_u32(smem);

    const __nv_bfloat16* srcA = g_xnbf + (size_t)m0 * D_SZ;
    const __nv_bfloat16* srcB = g_wn + (size_t)n0 * D_SZ;

    float acc[4][4][4];
    #pragma unroll
    for (int a = 0; a < 4; a++)
        #pragma unroll
        for (int b = 0; b < 4; b++)
            #pragma unroll
            for (int c = 0; c < 4; c++) acc[a][b][c] = 0.f;

    // stage loader: 2048 cp16 (A: 128x64 halves, B: 128x64 halves), 8/thread
    auto load_stage = [&](int stage, int k0) {
        const uint32_t dst = sb + (uint32_t)stage * STAGE_B;
        #pragma unroll
        for (int j = 0; j < 8; j++) {
            int idx = tid + 256 * j;            // 0..2047
            int row = (idx >> 3) & 127;
            int piece = idx & 7;
            uint32_t doff = (uint32_t)(row * (PITCH * 2) + piece * 16);
            if (idx < 1024)
                cp16(dst + doff, srcA + (size_t)row * D_SZ + k0 + piece * 8);
            else
                cp16(dst + B_PART + doff, srcB + (size_t)row * D_SZ + k0 + piece * 8);
        }
    };

    load_stage(0, 0);
    CP_COMMIT();
    load_stage(1, BK);
    CP_COMMIT();
    load_stage(2, 2 * BK);
    CP_COMMIT();

    const int lrow = lane & 15;
    const int lcol = (lane >> 4) * 8;

    #pragma unroll 1
    for (int k = 0; k < NK; k++) {
        // wait for stage k's data (tail steps have fewer groups in flight)
        if (k <= NK - 3)      { CP_WAIT(2); }
        else if (k == NK - 2) { CP_WAIT(1); }
        else                  { CP_WAIT(0); }
        __syncthreads();   // also orders: stage (k+3)%4 fully consumed at step k-1

        if (k + 3 < NK) {
            load_stage((k + 3) % NSTAGE, (k + 3) * BK);
            CP_COMMIT();
        }

        const uint32_t aoff = sb + (uint32_t)(k % NSTAGE) * STAGE_B;
        const uint32_t boff = aoff + B_PART;
        #pragma unroll
        for (int kk = 0; kk < BK; kk += 16) {
            uint32_t af[4][4], bf[2][4];
            #pragma unroll
            for (int mt = 0; mt < 4; mt++)
                ldsm4(af[mt], aoff + (uint32_t)((wm * 64 + mt * 16 + lrow) * PITCH + kk + lcol) * 2);
            #pragma unroll
            for (int nt2 = 0; nt2 < 2; nt2++)
                ldsm4(bf[nt2], boff + (uint32_t)((wn * 32 + nt2 * 16 + lrow) * PITCH + kk + lcol) * 2);
            #pragma unroll
            for (int mt = 0; mt < 4; mt++) {
                #pragma unroll
                for (int nt = 0; nt < 4; nt++) {
                    const uint32_t* bb = bf[nt >> 1];
                    uint32_t b0 = (nt & 1) ? bb[1] : bb[0];
                    uint32_t b1 = (nt & 1) ? bb[3] : bb[2];
                    mma16816(acc[mt][nt], af[mt], b0, b1);
                }
            }
        }
    }

    // ---- epilogue: exp-sum per batch row, atomic into g_rowsum -------------
    const bool edge = (n0 + BN > C_SZ);
    const int rbase = m0 + wm * 64 + (lane >> 2);
    const int cbase = n0 + wn * 32 + 2 * (lane & 3);

    #pragma unroll
    for (int mt = 0; mt < 4; mt++) {
        float es0 = 0.f, es1 = 0.f;
        #pragma unroll
        for (int nt = 0; nt < 4; nt++) {
            const int c0 = cbase + nt * 8;
            if (!edge) {
                es0 += __expf(fmaf(acc[mt][nt][0], S_SCALE, -LMAX));
                es0 += __expf(fmaf(acc[mt][nt][1], S_SCALE, -LMAX));
                es1 += __expf(fmaf(acc[mt][nt][2], S_SCALE, -LMAX));
                es1 += __expf(fmaf(acc[mt][nt][3], S_SCALE, -LMAX));
            } else {
                if (c0 < C_SZ)     { es0 += __expf(fmaf(acc[mt][nt][0], S_SCALE, -LMAX));
                                     es1 += __expf(fmaf(acc[mt][nt][2], S_SCALE, -LMAX)); }
                if (c0 + 1 < C_SZ) { es0 += __expf(fmaf(acc[mt][nt][1], S_SCALE, -LMAX));
                                     es1 += __expf(fmaf(acc[mt][nt][3], S_SCALE, -LMAX)); }
            }
        }
        es0 += __shfl_xor_sync(0xffffffffu, es0, 1);
        es0 += __shfl_xor_sync(0xffffffffu, es0, 2);
        es1 += __shfl_xor_sync(0xffffffffu, es1, 1);
        es1 += __shfl_xor_sync(0xffffffffu, es1, 2);
        if ((lane & 3) == 0) {
            atomicAdd(&g_rowsum[rbase + mt * 16], es0);
            atomicAdd(&g_rowsum[rbase + mt * 16 + 8], es1);
        }
    }
}

// ---------------------------------------------------------------------------
// Kernel 4: finalize — exact fp32 target dot + target norm, margin swap, nll.
// (target is int32: JAX x64-disabled downcasts int64 -> int32)
// ---------------------------------------------------------------------------
__global__ void finalize_kernel(const float* __restrict__ w,
                                const int* __restrict__ tgt) {
    const int b = blockIdx.x;
    const int tid = threadIdx.x;   // 256
    __shared__ float sd[256], sn[256];

    const int t = tgt[b];
    const float* wr = w + (size_t)t * D_SZ;
    const float* xr = g_xn + (size_t)b * D_SZ;
    float w0 = wr[tid], w1 = wr[tid + 256];
    sd[tid] = xr[tid] * w0 + xr[tid + 256] * w1;
    sn[tid] = w0 * w0 + w1 * w1;
    __syncthreads();
    #pragma unroll
    for (int off = 128; off > 0; off >>= 1) {
        if (tid < off) { sd[tid] += sd[tid + off]; sn[tid] += sn[tid + off]; }
        __syncthreads();
    }

    if (tid == 0) {
        float winv = 1.f / fmaxf(sqrtf(sn[0]), 1e-12f);
        float cosv = sd[0] * winv;
        float sinv = sqrtf(fmaxf(1.f - cosv * cosv, 0.f));
        float phi = cosv * COS_M - sinv * SIN_M;
        float adj = (cosv > 0.f) ? phi : cosv;          // easy margin
        float lt = S_SCALE * adj;
        float lo = S_SCALE * cosv;
        float s2 = g_rowsum[b] - expf(lo - LMAX) + expf(lt - LMAX);
        g_nll[b] = LMAX + logf(s2) - lt;
    }
}

// ---------------------------------------------------------------------------
// Kernel 5: mean over batch -> d_out[0]
// ---------------------------------------------------------------------------
__global__ void mean_kernel(float* __restrict__ out) {
    const int tid = threadIdx.x;   // 256
    __shared__ float sm[256];
    sm[tid] = g_nll[tid] + g_nll[tid + 256];
    __syncthreads();
    #pragma unroll
    for (int off = 128; off > 0; off >>= 1) {
        if (tid < off) sm[tid] += sm[tid + off];
        __syncthreads();
    }
    if (tid == 0) out[0] = sm[0] * (1.f / (float)B_SZ);
}

// ---------------------------------------------------------------------------
extern "C" void kernel_launch(void* const* d_in, const int* in_sizes, int n_in,
                              void* d_out, int out_size) {
    const float* x = (const float*)d_in[0];
    const float* w = (const float*)d_in[1];
    const int* tgt = (const int*)d_in[2];
    float* out = (float*)d_out;

    cudaFuncSetAttribute(gemm_fused_kernel,
                         cudaFuncAttributeMaxDynamicSharedMemorySize, SMEM_BYTES);

    xnorm_kernel<<<B_SZ, 128>>>(x);
    wconv_kernel<<<C_SZ / 8, 256>>>(w);
    dim3 grid(B_SZ / BM, NTILES_N);
    gemm_fused_kernel<<<grid, 256, SMEM_BYTES>>>();
    finalize_kernel<<<B_SZ, 256>>>(w, tgt);
    mean_kernel<<<1, 256>>>(out);
}

// round 8
// speedup vs baseline: 1.2447x; 1.2447x over previous
#include <cuda_runtime.h>
#include <cuda_bf16.h>
#include <math.h>
#include <stdint.h>

#define B_SZ 512
#define D_SZ 512
#define C_SZ 100000
#define BN 128
#define BM 128
#define BK 64
#define NK 8                       // 512/64
#define NSTAGE 3
#define NTILES_N 782               // ceil(100000/128)
#define C_PAD (NTILES_N * BN)      // 100096 (pad rows stay zero)
#define PITCH 72                   // halves per smem row (144 B) — conflict-free ldsm
#define STAGE_B (2 * 128 * PITCH * 2)      // A half + B half = 36864 B
#define B_PART  (128 * PITCH * 2)          // 18432
#define SMEM_BYTES (NSTAGE * STAGE_B)      // 110592
#define S_SCALE 30.0f
#define LMAX 31.0f
#define COS_M 0.8775825618903728f
#define SIN_M 0.47942553860420300f

// ---------------- static device scratch -------------------------------------
__device__ __nv_bfloat16 g_wn[(size_t)C_PAD * D_SZ];   // normalized bf16 w
__device__ __nv_bfloat16 g_xnbf[B_SZ * D_SZ];
__device__ float g_xn[B_SZ * D_SZ];
__device__ float g_rowsum[B_SZ];
__device__ float g_nll[B_SZ];

// ---------------- PTX helpers ------------------------------------------------
__device__ __forceinline__ uint32_t smem_u32(const void* p) {
    uint32_t a;
    asm("{ .reg .u64 t; cvta.to.shared.u64 t, %1; cvt.u32.u64 %0, t; }" : "=r"(a) : "l"(p));
    return a;
}
__device__ __forceinline__ void cp16(uint32_t dst, const void* src) {
    asm volatile("cp.async.cg.shared.global [%0], [%1], 16;" :: "r"(dst), "l"(src));
}
#define CP_COMMIT() asm volatile("cp.async.commit_group;" ::: "memory")
#define CP_WAIT(n)  asm volatile("cp.async.wait_group %0;" :: "n"(n) : "memory")

__device__ __forceinline__ void ldsm4(uint32_t* r, uint32_t addr) {
    asm volatile("ldmatrix.sync.aligned.m8n8.x4.shared.b16 {%0,%1,%2,%3}, [%4];"
        : "=r"(r[0]), "=r"(r[1]), "=r"(r[2]), "=r"(r[3]) : "r"(addr));
}
__device__ __forceinline__ void mma16816(float* d, const uint32_t* a, uint32_t b0, uint32_t b1) {
    asm volatile(
        "mma.sync.aligned.m16n8k16.row.col.f32.bf16.bf16.f32 "
        "{%0,%1,%2,%3}, {%4,%5,%6,%7}, {%8,%9}, {%0,%1,%2,%3};"
        : "+f"(d[0]), "+f"(d[1]), "+f"(d[2]), "+f"(d[3])
        : "r"(a[0]), "r"(a[1]), "r"(a[2]), "r"(a[3]), "r"(b0), "r"(b1));
}

// ---------------------------------------------------------------------------
// Kernel 1: normalize x rows -> g_xn (fp32) + g_xnbf (bf16); zero g_rowsum
// ---------------------------------------------------------------------------
__global__ void xnorm_kernel(const float* __restrict__ x) {
    const int row = blockIdx.x;
    const int tid = threadIdx.x;   // 128
    const float* xr = x + (size_t)row * D_SZ;

    float ss = 0.f;
    float v[4];
    #pragma unroll
    for (int i = 0; i < 4; i++) { v[i] = xr[tid + i * 128]; ss += v[i] * v[i]; }
    __shared__ float red[128];
    red[tid] = ss;
    __syncthreads();
    #pragma unroll
    for (int off = 64; off > 0; off >>= 1) {
        if (tid < off) red[tid] += red[tid + off];
        __syncthreads();
    }
    const float inv = 1.f / fmaxf(sqrtf(red[0]), 1e-12f);
    #pragma unroll
    for (int i = 0; i < 4; i++) {
        int d = tid + i * 128;
        float nv = v[i] * inv;
        g_xn[(size_t)row * D_SZ + d] = nv;
        g_xnbf[(size_t)row * D_SZ + d] = __float2bfloat16_rn(nv);
    }
    if (tid == 0) g_rowsum[row] = 0.f;
}

// ---------------------------------------------------------------------------
// Kernel 2: normalize weight rows + convert to bf16 (one warp per row)
// ---------------------------------------------------------------------------
__global__ void wconv_kernel(const float* __restrict__ w) {
    const int warp = threadIdx.x >> 5;
    const int lane = threadIdx.x & 31;
    const int c = blockIdx.x * 8 + warp;       // grid 12500 -> 100000 rows
    const float4* wr = reinterpret_cast<const float4*>(w + (size_t)c * D_SZ);

    float4 v[4];
    float ss = 0.f;
    #pragma unroll
    for (int i = 0; i < 4; i++) {
        v[i] = wr[lane + i * 32];
        ss += v[i].x * v[i].x + v[i].y * v[i].y + v[i].z * v[i].z + v[i].w * v[i].w;
    }
    #pragma unroll
    for (int m = 16; m > 0; m >>= 1)
        ss += __shfl_xor_sync(0xffffffffu, ss, m);
    const float inv = 1.f / fmaxf(sqrtf(ss), 1e-12f);

    uint2* dst = reinterpret_cast<uint2*>(g_wn + (size_t)c * D_SZ);
    #pragma unroll
    for (int i = 0; i < 4; i++) {
        __nv_bfloat162 p0 = __floats2bfloat162_rn(v[i].x * inv, v[i].y * inv);
        __nv_bfloat162 p1 = __floats2bfloat162_rn(v[i].z * inv, v[i].w * inv);
        uint2 o;
        o.x = *reinterpret_cast<uint32_t*>(&p0);
        o.y = *reinterpret_cast<uint32_t*>(&p1);
        dst[lane + i * 32] = o;
    }
}

// ---------------------------------------------------------------------------
// Kernel 3: fused HMMA GEMM + streaming exp-sum epilogue.
// CTA 128x128xK512. 3-stage cp.async ring, BK=64 (R6 pipeline, proven).
// Grid (m=4, n=782): the 4 CTAs sharing a B tile are consecutive -> L2 reuse.
// ---------------------------------------------------------------------------
__global__ void __launch_bounds__(256, 1) gemm_fused_kernel() {
    extern __shared__ __align__(16) char smem[];
    const int tid = threadIdx.x;
    const int warp = tid >> 5;
    const int lane = tid & 31;
    const int wm = warp & 1;
    const int wn = warp >> 1;
    const int m0 = blockIdx.x * BM;
    const int n0 = blockIdx.y * BN;
    const uint32_t sb = smem_u32(smem);

    const __nv_bfloat16* srcA = g_xnbf + (size_t)m0 * D_SZ;
    const __nv_bfloat16* srcB = g_wn + (size_t)n0 * D_SZ;

    float acc[4][4][4];
    #pragma unroll
    for (int a = 0; a < 4; a++)
        #pragma unroll
        for (int b = 0; b < 4; b++)
            #pragma unroll
            for (int c = 0; c < 4; c++) acc[a][b][c] = 0.f;

    // stage loader: 2048 cp16 (A: 128x64 halves, B: 128x64 halves), 8/thread
    auto load_stage = [&](int stage, int k0) {
        const uint32_t dst = sb + (uint32_t)stage * STAGE_B;
        #pragma unroll
        for (int j = 0; j < 8; j++) {
            int idx = tid + 256 * j;            // 0..2047
            int row = (idx >> 3) & 127;
            int piece = idx & 7;
            uint32_t doff = (uint32_t)(row * (PITCH * 2) + piece * 16);
            if (idx < 1024)
                cp16(dst + doff, srcA + (size_t)row * D_SZ + k0 + piece * 8);
            else
                cp16(dst + B_PART + doff, srcB + (size_t)row * D_SZ + k0 + piece * 8);
        }
    };

    load_stage(0, 0);
    CP_COMMIT();
    load_stage(1, BK);
    CP_COMMIT();

    const int lrow = lane & 15;
    const int lcol = (lane >> 4) * 8;

    for (int k = 0; k < NK; k++) {
        if (k == NK - 1) { CP_WAIT(0); } else { CP_WAIT(1); }
        __syncthreads();

        const uint32_t aoff = sb + (uint32_t)(k % NSTAGE) * STAGE_B;
        const uint32_t boff = aoff + B_PART;
        #pragma unroll
        for (int kk = 0; kk < BK; kk += 16) {
            uint32_t af[4][4], bf[2][4];
            #pragma unroll
            for (int mt = 0; mt < 4; mt++)
                ldsm4(af[mt], aoff + (uint32_t)((wm * 64 + mt * 16 + lrow) * PITCH + kk + lcol) * 2);
            #pragma unroll
            for (int nt2 = 0; nt2 < 2; nt2++)
                ldsm4(bf[nt2], boff + (uint32_t)((wn * 32 + nt2 * 16 + lrow) * PITCH + kk + lcol) * 2);
            #pragma unroll
            for (int mt = 0; mt < 4; mt++) {
                #pragma unroll
                for (int nt = 0; nt < 4; nt++) {
                    const uint32_t* bb = bf[nt >> 1];
                    uint32_t b0 = (nt & 1) ? bb[1] : bb[0];
                    uint32_t b1 = (nt & 1) ? bb[3] : bb[2];
                    mma16816(acc[mt][nt], af[mt], b0, b1);
                }
            }
        }
        __syncthreads();   // all warps done reading stage k before it is refilled

        if (k + 2 < NK) {
            load_stage((k + 2) % NSTAGE, (k + 2) * BK);
            CP_COMMIT();
        }
    }

    // ---- epilogue: exp-sum per batch row, atomic into g_rowsum -------------
    const bool edge = (n0 + BN > C_SZ);
    const int rbase = m0 + wm * 64 + (lane >> 2);
    const int cbase = n0 + wn * 32 + 2 * (lane & 3);

    #pragma unroll
    for (int mt = 0; mt < 4; mt++) {
        float es0 = 0.f, es1 = 0.f;
        #pragma unroll
        for (int nt = 0; nt < 4; nt++) {
            const int c0 = cbase + nt * 8;
            if (!edge) {
                es0 += __expf(fmaf(acc[mt][nt][0], S_SCALE, -LMAX));
                es0 += __expf(fmaf(acc[mt][nt][1], S_SCALE, -LMAX));
                es1 += __expf(fmaf(acc[mt][nt][2], S_SCALE, -LMAX));
                es1 += __expf(fmaf(acc[mt][nt][3], S_SCALE, -LMAX));
            } else {
                if (c0 < C_SZ)     { es0 += __expf(fmaf(acc[mt][nt][0], S_SCALE, -LMAX));
                                     es1 += __expf(fmaf(acc[mt][nt][2], S_SCALE, -LMAX)); }
                if (c0 + 1 < C_SZ) { es0 += __expf(fmaf(acc[mt][nt][1], S_SCALE, -LMAX));
                                     es1 += __expf(fmaf(acc[mt][nt][3], S_SCALE, -LMAX)); }
            }
        }
        es0 += __shfl_xor_sync(0xffffffffu, es0, 1);
        es0 += __shfl_xor_sync(0xffffffffu, es0, 2);
        es1 += __shfl_xor_sync(0xffffffffu, es1, 1);
        es1 += __shfl_xor_sync(0xffffffffu, es1, 2);
        if ((lane & 3) == 0) {
            atomicAdd(&g_rowsum[rbase + mt * 16], es0);
            atomicAdd(&g_rowsum[rbase + mt * 16 + 8], es1);
        }
    }
}

// ---------------------------------------------------------------------------
// Kernel 4: finalize — exact fp32 target dot + target norm, margin swap, nll.
// (target is int32: JAX x64-disabled downcasts int64 -> int32)
// ---------------------------------------------------------------------------
__global__ void finalize_kernel(const float* __restrict__ w,
                                const int* __restrict__ tgt) {
    const int b = blockIdx.x;
    const int tid = threadIdx.x;   // 256
    __shared__ float sd[256], sn[256];

    const int t = tgt[b];
    const float* wr = w + (size_t)t * D_SZ;
    const float* xr = g_xn + (size_t)b * D_SZ;
    float w0 = wr[tid], w1 = wr[tid + 256];
    sd[tid] = xr[tid] * w0 + xr[tid + 256] * w1;
    sn[tid] = w0 * w0 + w1 * w1;
    __syncthreads();
    #pragma unroll
    for (int off = 128; off > 0; off >>= 1) {
        if (tid < off) { sd[tid] += sd[tid + off]; sn[tid] += sn[tid + off]; }
        __syncthreads();
    }

    if (tid == 0) {
        float winv = 1.f / fmaxf(sqrtf(sn[0]), 1e-12f);
        float cosv = sd[0] * winv;
        float sinv = sqrtf(fmaxf(1.f - cosv * cosv, 0.f));
        float phi = cosv * COS_M - sinv * SIN_M;
        float adj = (cosv > 0.f) ? phi : cosv;          // easy margin
        float lt = S_SCALE * adj;
        float lo = S_SCALE * cosv;
        float s2 = g_rowsum[b] - expf(lo - LMAX) + expf(lt - LMAX);
        g_nll[b] = LMAX + logf(s2) - lt;
    }
}

// ---------------------------------------------------------------------------
// Kernel 5: mean over batch -> d_out[0]
// ---------------------------------------------------------------------------
__global__ void mean_kernel(float* __restrict__ out) {
    const int tid = threadIdx.x;   // 256
    __shared__ float sm[256];
    sm[tid] = g_nll[tid] + g_nll[tid + 256];
    __syncthreads();
    #pragma unroll
    for (int off = 128; off > 0; off >>= 1) {
        if (tid < off) sm[tid] += sm[tid + off];
        __syncthreads();
    }
    if (tid == 0) out[0] = sm[0] * (1.f / (float)B_SZ);
}

// ---------------------------------------------------------------------------
extern "C" void kernel_launch(void* const* d_in, const int* in_sizes, int n_in,
                              void* d_out, int out_size) {
    const float* x = (const float*)d_in[0];
    const float* w = (const float*)d_in[1];
    const int* tgt = (const int*)d_in[2];
    float* out = (float*)d_out;

    cudaFuncSetAttribute(gemm_fused_kernel,
                         cudaFuncAttributeMaxDynamicSharedMemorySize, SMEM_BYTES);

    xnorm_kernel<<<B_SZ, 128>>>(x);
    wconv_kernel<<<C_SZ / 8, 256>>>(w);
    dim3 grid(B_SZ / BM, NTILES_N);
    gemm_fused_kernel<<<grid, 256, SMEM_BYTES>>>();
    finalize_kernel<<<B_SZ, 256>>>(w, tgt);
    mean_kernel<<<1, 256>>>(out);
}

// round 9
// speedup vs baseline: 1.2539x; 1.0073x over previous
#include <cuda_runtime.h>
#include <cuda_bf16.h>
#include <math.h>
#include <stdint.h>

#define B_SZ 512
#define D_SZ 512
#define C_SZ 100000
#define BN 128
#define BM 128
#define BK 64
#define NK 8                       // 512/64
#define NSTAGE 3
#define NTILES_N 782               // ceil(100000/128)
#define C_PAD (NTILES_N * BN)      // 100096 (pad rows stay zero)
#define PITCH 72                   // halves per smem row (144 B) — conflict-free ldsm
#define STAGE_B (2 * 128 * PITCH * 2)      // A half + B half = 36864 B
#define B_PART  (128 * PITCH * 2)          // 18432
#define SMEM_BYTES (NSTAGE * STAGE_B)      // 110592
#define S_SCALE 30.0f
#define LMAX 31.0f
#define COS_M 0.8775825618903728f
#define SIN_M 0.47942553860420300f

// ---------------- static device scratch -------------------------------------
__device__ __nv_bfloat16 g_wn[(size_t)C_PAD * D_SZ];   // normalized bf16 w
__device__ __nv_bfloat16 g_xnbf[B_SZ * D_SZ];
__device__ float g_xn[B_SZ * D_SZ];
__device__ float g_rowsum[B_SZ];

// ---------------- PTX helpers ------------------------------------------------
__device__ __forceinline__ uint32_t smem_u32(const void* p) {
    uint32_t a;
    asm("{ .reg .u64 t; cvta.to.shared.u64 t, %1; cvt.u32.u64 %0, t; }" : "=r"(a) : "l"(p));
    return a;
}
__device__ __forceinline__ void cp16(uint32_t dst, const void* src) {
    asm volatile("cp.async.cg.shared.global [%0], [%1], 16;" :: "r"(dst), "l"(src));
}
#define CP_COMMIT() asm volatile("cp.async.commit_group;" ::: "memory")
#define CP_WAIT(n)  asm volatile("cp.async.wait_group %0;" :: "n"(n) : "memory")

__device__ __forceinline__ void ldsm4(uint32_t* r, uint32_t addr) {
    asm volatile("ldmatrix.sync.aligned.m8n8.x4.shared.b16 {%0,%1,%2,%3}, [%4];"
        : "=r"(r[0]), "=r"(r[1]), "=r"(r[2]), "=r"(r[3]) : "r"(addr));
}
__device__ __forceinline__ void mma16816(float* d, const uint32_t* a, uint32_t b0, uint32_t b1) {
    asm volatile(
        "mma.sync.aligned.m16n8k16.row.col.f32.bf16.bf16.f32 "
        "{%0,%1,%2,%3}, {%4,%5,%6,%7}, {%8,%9}, {%0,%1,%2,%3};"
        : "+f"(d[0]), "+f"(d[1]), "+f"(d[2]), "+f"(d[3])
        : "r"(a[0]), "r"(a[1]), "r"(a[2]), "r"(a[3]), "r"(b0), "r"(b1));
}

// ---------------------------------------------------------------------------
// Kernel 1: normalize x rows -> g_xn (fp32) + g_xnbf (bf16); zero g_rowsum
// and the output scalar (block 0).
// ---------------------------------------------------------------------------
__global__ void xnorm_kernel(const float* __restrict__ x, float* __restrict__ out) {
    const int row = blockIdx.x;
    const int tid = threadIdx.x;   // 128
    const float* xr = x + (size_t)row * D_SZ;

    float ss = 0.f;
    float v[4];
    #pragma unroll
    for (int i = 0; i < 4; i++) { v[i] = xr[tid + i * 128]; ss += v[i] * v[i]; }
    __shared__ float red[128];
    red[tid] = ss;
    __syncthreads();
    #pragma unroll
    for (int off = 64; off > 0; off >>= 1) {
        if (tid < off) red[tid] += red[tid + off];
        __syncthreads();
    }
    const float inv = 1.f / fmaxf(sqrtf(red[0]), 1e-12f);
    #pragma unroll
    for (int i = 0; i < 4; i++) {
        int d = tid + i * 128;
        float nv = v[i] * inv;
        g_xn[(size_t)row * D_SZ + d] = nv;
        g_xnbf[(size_t)row * D_SZ + d] = __float2bfloat16_rn(nv);
    }
    if (tid == 0) {
        g_rowsum[row] = 0.f;
        if (row == 0) out[0] = 0.f;
    }
}

// ---------------------------------------------------------------------------
// Kernel 2: normalize weight rows + convert to bf16 (one warp per row)
// ---------------------------------------------------------------------------
__global__ void wconv_kernel(const float* __restrict__ w) {
    const int warp = threadIdx.x >> 5;
    const int lane = threadIdx.x & 31;
    const int c = blockIdx.x * 8 + warp;       // grid 12500 -> 100000 rows
    const float4* wr = reinterpret_cast<const float4*>(w + (size_t)c * D_SZ);

    float4 v[4];
    float ss = 0.f;
    #pragma unroll
    for (int i = 0; i < 4; i++) {
        v[i] = wr[lane + i * 32];
        ss += v[i].x * v[i].x + v[i].y * v[i].y + v[i].z * v[i].z + v[i].w * v[i].w;
    }
    #pragma unroll
    for (int m = 16; m > 0; m >>= 1)
        ss += __shfl_xor_sync(0xffffffffu, ss, m);
    const float inv = 1.f / fmaxf(sqrtf(ss), 1e-12f);

    uint2* dst = reinterpret_cast<uint2*>(g_wn + (size_t)c * D_SZ);
    #pragma unroll
    for (int i = 0; i < 4; i++) {
        __nv_bfloat162 p0 = __floats2bfloat162_rn(v[i].x * inv, v[i].y * inv);
        __nv_bfloat162 p1 = __floats2bfloat162_rn(v[i].z * inv, v[i].w * inv);
        uint2 o;
        o.x = *reinterpret_cast<uint32_t*>(&p0);
        o.y = *reinterpret_cast<uint32_t*>(&p1);
        dst[lane + i * 32] = o;
    }
}

// ---------------------------------------------------------------------------
// Kernel 3: fused HMMA GEMM + streaming exp-sum epilogue.
// CTA 128x128xK512. 3-stage cp.async ring, BK=64 (R6/R8 pipeline, proven).
// Grid (m=4, n=782). __launch_bounds__(256, 2): 2 CTAs/SM to overlap
// epilogue/fill/barrier bubbles across co-resident CTAs.
// ---------------------------------------------------------------------------
__global__ void __launch_bounds__(256, 2) gemm_fused_kernel() {
    extern __shared__ __align__(16) char smem[];
    const int tid = threadIdx.x;
    const int warp = tid >> 5;
    const int lane = tid & 31;
    const int wm = warp & 1;
    const int wn = warp >> 1;
    const int m0 = blockIdx.x * BM;
    const int n0 = blockIdx.y * BN;
    const uint32_t sb = smem_u32(smem);

    const __nv_bfloat16* srcA = g_xnbf + (size_t)m0 * D_SZ;
    const __nv_bfloat16* srcB = g_wn + (size_t)n0 * D_SZ;

    float acc[4][4][4];
    #pragma unroll
    for (int a = 0; a < 4; a++)
        #pragma unroll
        for (int b = 0; b < 4; b++)
            #pragma unroll
            for (int c = 0; c < 4; c++) acc[a][b][c] = 0.f;

    // stage loader: 2048 cp16 (A: 128x64 halves, B: 128x64 halves), 8/thread
    auto load_stage = [&](int stage, int k0) {
        const uint32_t dst = sb + (uint32_t)stage * STAGE_B;
        #pragma unroll
        for (int j = 0; j < 8; j++) {
            int idx = tid + 256 * j;            // 0..2047
            int row = (idx >> 3) & 127;
            int piece = idx & 7;
            uint32_t doff = (uint32_t)(row * (PITCH * 2) + piece * 16);
            if (idx < 1024)
                cp16(dst + doff, srcA + (size_t)row * D_SZ + k0 + piece * 8);
            else
                cp16(dst + B_PART + doff, srcB + (size_t)row * D_SZ + k0 + piece * 8);
        }
    };

    load_stage(0, 0);
    CP_COMMIT();
    load_stage(1, BK);
    CP_COMMIT();

    const int lrow = lane & 15;
    const int lcol = (lane >> 4) * 8;

    for (int k = 0; k < NK; k++) {
        if (k == NK - 1) { CP_WAIT(0); } else { CP_WAIT(1); }
        __syncthreads();

        const uint32_t aoff = sb + (uint32_t)(k % NSTAGE) * STAGE_B;
        const uint32_t boff = aoff + B_PART;
        #pragma unroll
        for (int kk = 0; kk < BK; kk += 16) {
            uint32_t af[4][4], bf[2][4];
            #pragma unroll
            for (int mt = 0; mt < 4; mt++)
                ldsm4(af[mt], aoff + (uint32_t)((wm * 64 + mt * 16 + lrow) * PITCH + kk + lcol) * 2);
            #pragma unroll
            for (int nt2 = 0; nt2 < 2; nt2++)
                ldsm4(bf[nt2], boff + (uint32_t)((wn * 32 + nt2 * 16 + lrow) * PITCH + kk + lcol) * 2);
            #pragma unroll
            for (int mt = 0; mt < 4; mt++) {
                #pragma unroll
                for (int nt = 0; nt < 4; nt++) {
                    const uint32_t* bb = bf[nt >> 1];
                    uint32_t b0 = (nt & 1) ? bb[1] : bb[0];
                    uint32_t b1 = (nt & 1) ? bb[3] : bb[2];
                    mma16816(acc[mt][nt], af[mt], b0, b1);
                }
            }
        }
        __syncthreads();   // all warps done reading stage k before it is refilled

        if (k + 2 < NK) {
            load_stage((k + 2) % NSTAGE, (k + 2) * BK);
            CP_COMMIT();
        }
    }

    // ---- epilogue: exp-sum per batch row, atomic into g_rowsum -------------
    const bool edge = (n0 + BN > C_SZ);
    const int rbase = m0 + wm * 64 + (lane >> 2);
    const int cbase = n0 + wn * 32 + 2 * (lane & 3);

    #pragma unroll
    for (int mt = 0; mt < 4; mt++) {
        float es0 = 0.f, es1 = 0.f;
        #pragma unroll
        for (int nt = 0; nt < 4; nt++) {
            const int c0 = cbase + nt * 8;
            if (!edge) {
                es0 += __expf(fmaf(acc[mt][nt][0], S_SCALE, -LMAX));
                es0 += __expf(fmaf(acc[mt][nt][1], S_SCALE, -LMAX));
                es1 += __expf(fmaf(acc[mt][nt][2], S_SCALE, -LMAX));
                es1 += __expf(fmaf(acc[mt][nt][3], S_SCALE, -LMAX));
            } else {
                if (c0 < C_SZ)     { es0 += __expf(fmaf(acc[mt][nt][0], S_SCALE, -LMAX));
                                     es1 += __expf(fmaf(acc[mt][nt][2], S_SCALE, -LMAX)); }
                if (c0 + 1 < C_SZ) { es0 += __expf(fmaf(acc[mt][nt][1], S_SCALE, -LMAX));
                                     es1 += __expf(fmaf(acc[mt][nt][3], S_SCALE, -LMAX)); }
            }
        }
        es0 += __shfl_xor_sync(0xffffffffu, es0, 1);
        es0 += __shfl_xor_sync(0xffffffffu, es0, 2);
        es1 += __shfl_xor_sync(0xffffffffu, es1, 1);
        es1 += __shfl_xor_sync(0xffffffffu, es1, 2);
        if ((lane & 3) == 0) {
            atomicAdd(&g_rowsum[rbase + mt * 16], es0);
            atomicAdd(&g_rowsum[rbase + mt * 16 + 8], es1);
        }
    }
}

// ---------------------------------------------------------------------------
// Kernel 4: finalize — exact fp32 target dot + target norm, margin swap, nll;
// atomic mean accumulation into out[0] (zeroed by xnorm).
// ---------------------------------------------------------------------------
__global__ void finalize_kernel(const float* __restrict__ w,
                                const int* __restrict__ tgt,
                                float* __restrict__ out) {
    const int b = blockIdx.x;
    const int tid = threadIdx.x;   // 256
    __shared__ float sd[256], sn[256];

    const int t = tgt[b];
    const float* wr = w + (size_t)t * D_SZ;
    const float* xr = g_xn + (size_t)b * D_SZ;
    float w0 = wr[tid], w1 = wr[tid + 256];
    sd[tid] = xr[tid] * w0 + xr[tid + 256] * w1;
    sn[tid] = w0 * w0 + w1 * w1;
    __syncthreads();
    #pragma unroll
    for (int off = 128; off > 0; off >>= 1) {
        if (tid < off) { sd[tid] += sd[tid + off]; sn[tid] += sn[tid + off]; }
        __syncthreads();
    }

    if (tid == 0) {
        float winv = 1.f / fmaxf(sqrtf(sn[0]), 1e-12f);
        float cosv = sd[0] * winv;
        float sinv = sqrtf(fmaxf(1.f - cosv * cosv, 0.f));
        float phi = cosv * COS_M - sinv * SIN_M;
        float adj = (cosv > 0.f) ? phi : cosv;          // easy margin
        float lt = S_SCALE * adj;
        float lo = S_SCALE * cosv;
        float s2 = g_rowsum[b] - expf(lo - LMAX) + expf(lt - LMAX);
        float nll = LMAX + logf(s2) - lt;
        atomicAdd(out, nll * (1.f / (float)B_SZ));
    }
}

// ---------------------------------------------------------------------------
extern "C" void kernel_launch(void* const* d_in, const int* in_sizes, int n_in,
                              void* d_out, int out_size) {
    const float* x = (const float*)d_in[0];
    const float* w = (const float*)d_in[1];
    const int* tgt = (const int*)d_in[2];
    float* out = (float*)d_out;

    cudaFuncSetAttribute(gemm_fused_kernel,
                         cudaFuncAttributeMaxDynamicSharedMemorySize, SMEM_BYTES);

    xnorm_kernel<<<B_SZ, 128>>>(x, out);
    wconv_kernel<<<C_SZ / 8, 256>>>(w);
    dim3 grid(B_SZ / BM, NTILES_N);
    gemm_fused_kernel<<<grid, 256, SMEM_BYTES>>>();
    finalize_kernel<<<B_SZ, 256>>>(w, tgt, out);
}